// round 2
// baseline (speedup 1.0000x reference)
#include <cuda_runtime.h>
#include <cuda_bf16.h>
#include <math.h>

// ---------------- problem constants (fixed by reference) ----------------
#define NN      100000      // N_NODES
#define NE      1600000     // N_EDGES
#define HID     64
#define INC     256
#define OUTC    32
#define KORD    10
#define NLAYERS 2
#define NBLK_SCAN 391       // ceil(NN/256)

// ---------------- device scratch (static globals: allowed) --------------
__device__ int   g_is64;            // edge_index dtype flag (1 = int64, 0 = int32)
__device__ int   g_deg[NN];
__device__ float g_dinv[NN];
__device__ int   g_off[NN + 1];
__device__ int   g_cur[NN];
__device__ int   g_src[NE];
__device__ int   g_bsum[512];

__device__ float g_T[3][NN * HID];   // Jacobi term ring buffer (Tx0/Tx1/Tx2)
__device__ float g_G[2][NN * HID];   // pre-scaled (dinv * t) ping-pong
__device__ float g_OUT[NN * HID];    // per-layer accumulated output

// ======================= edge dtype detection =======================
// If edge_index is int64 (little-endian, values < 2^31), every odd 32-bit
// word is 0. If int32, odd words are random node ids in [0, NN) — the odds
// that 4096 of them are all zero is ~0. One block, deterministic.
__global__ void detect_dtype_kernel(const int* __restrict__ ei32) {
    __shared__ int any_nonzero;
    if (threadIdx.x == 0) any_nonzero = 0;
    __syncthreads();
    for (int i = threadIdx.x; i < 4096; i += 256) {
        if (ei32[2 * i + 1] != 0) any_nonzero = 1;
    }
    __syncthreads();
    if (threadIdx.x == 0) g_is64 = (any_nonzero == 0) ? 1 : 0;
}

__device__ __forceinline__ int edge_at(const void* __restrict__ ei, int idx, int is64) {
    if (is64) return (int)((const long long*)ei)[idx];
    return ((const int*)ei)[idx];
}

// ======================= CSR build =======================

__global__ void zero_deg_kernel() {
    int i = blockIdx.x * 256 + threadIdx.x;
    if (i < NN) g_deg[i] = 0;
}

__global__ void count_deg_kernel(const void* __restrict__ ei) {
    int is64 = g_is64;
    int e = blockIdx.x * 256 + threadIdx.x;
    if (e < NE) {
        int c = edge_at(ei, NE + e, is64);   // edge_index[1][e]
        atomicAdd(&g_deg[c], 1);
    }
}

__global__ void dinv_kernel() {
    int i = blockIdx.x * 256 + threadIdx.x;
    if (i < NN) {
        float d = (float)(g_deg[i] + 1);     // +1 self loop
        g_dinv[i] = rsqrtf(d);
    }
}

__global__ void scan1_kernel() {
    __shared__ int sh[256];
    int tid = threadIdx.x;
    int i = blockIdx.x * 256 + tid;
    int v = (i < NN) ? g_deg[i] : 0;
    sh[tid] = v;
    __syncthreads();
#pragma unroll
    for (int o = 1; o < 256; o <<= 1) {
        int t = (tid >= o) ? sh[tid - o] : 0;
        __syncthreads();
        sh[tid] += t;
        __syncthreads();
    }
    if (i < NN) g_off[i] = sh[tid] - v;      // block-local exclusive
    if (tid == 255) g_bsum[blockIdx.x] = sh[255];
}

__global__ void scan2_kernel() {
    __shared__ int sh[512];
    int tid = threadIdx.x;
    int v = (tid < NBLK_SCAN) ? g_bsum[tid] : 0;
    sh[tid] = v;
    __syncthreads();
#pragma unroll
    for (int o = 1; o < 512; o <<= 1) {
        int t = (tid >= o) ? sh[tid - o] : 0;
        __syncthreads();
        sh[tid] += t;
        __syncthreads();
    }
    if (tid < NBLK_SCAN) g_bsum[tid] = sh[tid];    // inclusive block sums
}

__global__ void scan3_kernel() {
    int i = blockIdx.x * 256 + threadIdx.x;
    if (i < NN) {
        int add = (blockIdx.x > 0) ? g_bsum[blockIdx.x - 1] : 0;
        int o = g_off[i] + add;
        g_off[i] = o;
        g_cur[i] = o;
    }
    if (i == 0) g_off[NN] = NE;
}

__global__ void scatter_kernel(const void* __restrict__ ei) {
    int is64 = g_is64;
    int e = blockIdx.x * 256 + threadIdx.x;
    if (e < NE) {
        int r = edge_at(ei, e, is64);
        int c = edge_at(ei, NE + e, is64);
        int p = atomicAdd(&g_cur[c], 1);
        g_src[p] = r;
    }
}

// ======================= GEMM1: h = relu(x @ W1 + b1); G0 = dinv*h =======
// 64x64 output tile, 256 threads (16x16), 4x4 register micro-tile, K-chunks of 16.

__global__ __launch_bounds__(256) void gemm1_kernel(const float* __restrict__ x,
                                                    const float* __restrict__ W1,
                                                    const float* __restrict__ b1) {
    __shared__ __align__(16) float xs[64][17];   // padded: conflict-free column reads
    __shared__ __align__(16) float ws[16][64];
    int tx = threadIdx.x & 15;     // col group
    int ty = threadIdx.x >> 4;     // row group
    int row0 = blockIdx.x * 64;

    float acc[4][4];
#pragma unroll
    for (int i = 0; i < 4; i++)
#pragma unroll
        for (int j = 0; j < 4; j++) acc[i][j] = 0.f;

    for (int kc = 0; kc < INC; kc += 16) {
        for (int l = threadIdx.x; l < 64 * 16; l += 256) {
            int r = l >> 4, k = l & 15;
            int gr = row0 + r;
            xs[r][k] = (gr < NN) ? x[gr * INC + kc + k] : 0.f;
        }
        for (int l = threadIdx.x; l < 16 * 64; l += 256) {
            int k = l >> 6, c = l & 63;
            ws[k][c] = W1[(kc + k) * HID + c];
        }
        __syncthreads();
#pragma unroll
        for (int k = 0; k < 16; k++) {
            float xv[4];
#pragma unroll
            for (int i = 0; i < 4; i++) xv[i] = xs[ty * 4 + i][k];
            float wv[4];
#pragma unroll
            for (int j = 0; j < 4; j++) wv[j] = ws[k][tx * 4 + j];
#pragma unroll
            for (int i = 0; i < 4; i++)
#pragma unroll
                for (int j = 0; j < 4; j++) acc[i][j] += xv[i] * wv[j];
        }
        __syncthreads();
    }

#pragma unroll
    for (int i = 0; i < 4; i++) {
        int gr = row0 + ty * 4 + i;
        if (gr < NN) {
            float dv = g_dinv[gr];
#pragma unroll
            for (int j = 0; j < 4; j++) {
                int c = tx * 4 + j;
                float h = fmaxf(acc[i][j] + b1[c], 0.f);
                g_T[0][gr * HID + c] = h;
                g_G[0][gr * HID + c] = dv * h;
            }
        }
    }
}

// ======================= Jacobi propagation (hot loop) ===================
// One block (64 threads) per node; thread = channel. Gather pre-scaled g,
// zero atomics, coalesced 256B row reads from L2, unroll-4 for MLP.

__global__ __launch_bounds__(64) void prop_first_kernel(const float* __restrict__ coeffs,
                                                        int base) {
    int node = blockIdx.x;
    int c = threadIdx.x;
    const float* __restrict__ g = g_G[0];
    const int* __restrict__ src = g_src;

    float a0 = g[node * HID + c];   // self loop
    float a1 = 0.f, a2 = 0.f, a3 = 0.f;
    int s = g_off[node], e = g_off[node + 1];
    int j = s;
    for (; j + 4 <= e; j += 4) {
        int s0 = src[j], s1 = src[j + 1], s2 = src[j + 2], s3 = src[j + 3];
        a0 += g[s0 * HID + c];
        a1 += g[s1 * HID + c];
        a2 += g[s2 * HID + c];
        a3 += g[s3 * HID + c];
    }
    for (; j < e; j++) a0 += g[src[j] * HID + c];

    float dv = g_dinv[node];
    float t1 = dv * (a0 + a1 + a2 + a3);
    int idx = node * HID + c;
    float h = g_T[0][idx];
    float c0 = coeffs[base], c1 = coeffs[base + 1];
    g_T[1][idx] = t1;
    g_OUT[idx] = c0 * h + c1 * t1;
    g_G[1][idx] = dv * t1;
}

__global__ __launch_bounds__(64) void prop_step_kernel(const float* __restrict__ coeffs,
                                                       int base,
                                                       float An, float Bn, float Cn,
                                                       int i1, int i0, int i2,
                                                       int igi, int igo) {
    int node = blockIdx.x;
    int c = threadIdx.x;
    const float* __restrict__ g = g_G[igi];
    const int* __restrict__ src = g_src;

    float a0 = g[node * HID + c];   // self loop
    float a1 = 0.f, a2 = 0.f, a3 = 0.f;
    int s = g_off[node], e = g_off[node + 1];
    int j = s;
    for (; j + 4 <= e; j += 4) {
        int s0 = src[j], s1 = src[j + 1], s2 = src[j + 2], s3 = src[j + 3];
        a0 += g[s0 * HID + c];
        a1 += g[s1 * HID + c];
        a2 += g[s2 * HID + c];
        a3 += g[s3 * HID + c];
    }
    for (; j < e; j++) a0 += g[src[j] * HID + c];

    float dv = g_dinv[node];
    float p = dv * (a0 + a1 + a2 + a3);     // (P t1)[node][c]
    int idx = node * HID + c;
    float t1 = g_T[i1][idx];
    float t0 = g_T[i0][idx];
    float t2 = An * p + Bn * t1 - Cn * t0;
    float ck = coeffs[base];
    g_T[i2][idx] = t2;
    g_OUT[idx] += ck * t2;
    g_G[igo][idx] = dv * t2;
}

// relu between layers: H = relu(OUT); G0 = dinv * H  (into T[0], G[0])
__global__ void layer_epi_kernel() {
    int i = blockIdx.x * 256 + threadIdx.x;
    if (i < NN * HID) {
        float h = fmaxf(g_OUT[i], 0.f);
        g_T[0][i] = h;
        g_G[0][i] = g_dinv[i >> 6] * h;
    }
}

// ======================= GEMM2: out = H @ W2 + b2 ========================
__global__ __launch_bounds__(256) void gemm2_kernel(const float* __restrict__ W2,
                                                    const float* __restrict__ b2,
                                                    float* __restrict__ out) {
    __shared__ __align__(16) float ws[64][32];
    __shared__ __align__(16) float xs[32][65];
    int tx = threadIdx.x & 31;   // col
    int ty = threadIdx.x >> 5;   // row group (0..7), 4 rows each
    int row0 = blockIdx.x * 32;

    for (int l = threadIdx.x; l < 64 * 32; l += 256) ws[l >> 5][l & 31] = W2[l];
    for (int l = threadIdx.x; l < 32 * 64; l += 256) {
        int r = l >> 6, k = l & 63;
        int gr = row0 + r;
        xs[r][k] = (gr < NN) ? g_T[0][gr * HID + k] : 0.f;
    }
    __syncthreads();

    float acc[4] = {0.f, 0.f, 0.f, 0.f};
#pragma unroll
    for (int k = 0; k < 64; k++) {
        float w = ws[k][tx];
#pragma unroll
        for (int i = 0; i < 4; i++) acc[i] += xs[ty * 4 + i][k] * w;
    }
    float bb = b2[tx];
#pragma unroll
    for (int i = 0; i < 4; i++) {
        int gr = row0 + ty * 4 + i;
        if (gr < NN) out[gr * OUTC + tx] = acc[i] + bb;
    }
}

// ======================= launcher =======================

extern "C" void kernel_launch(void* const* d_in, const int* in_sizes, int n_in,
                              void* d_out, int out_size) {
    const float* x      = (const float*)d_in[0];
    const void*  ei     = d_in[1];                 // int32 or int64, detected on device
    const float* W1     = (const float*)d_in[2];
    const float* b1     = (const float*)d_in[3];
    const float* coeffs = (const float*)d_in[4];
    const float* W2     = (const float*)d_in[5];
    const float* b2     = (const float*)d_in[6];
    float*       out    = (float*)d_out;

    // ---- detect edge dtype, then build norm + CSR ----
    detect_dtype_kernel<<<1, 256>>>((const int*)ei);
    zero_deg_kernel<<<NBLK_SCAN, 256>>>();
    count_deg_kernel<<<NE / 256, 256>>>(ei);
    dinv_kernel<<<NBLK_SCAN, 256>>>();
    scan1_kernel<<<NBLK_SCAN, 256>>>();
    scan2_kernel<<<1, 512>>>();
    scan3_kernel<<<NBLK_SCAN, 256>>>();
    scatter_kernel<<<NE / 256, 256>>>(ei);

    // ---- input projection ----
    gemm1_kernel<<<(NN + 63) / 64, 256>>>(x, W1, b1);

    // ---- Jacobi layers ----
    const double a = 0.5, b = 0.5;
    for (int l = 0; l < NLAYERS; l++) {
        int base = l * (KORD + 1);
        prop_first_kernel<<<NN, 64>>>(coeffs, base);
        int i1 = 1, i0 = 0;
        for (int k = 2; k <= KORD; k++) {
            double n = (double)(k - 1);
            double An = (2 * n + a + b + 1) * (2 * n + a + b + 2)
                        / (2 * (n + 1) * (n + a + b + 1));
            double Bn = (a * a - b * b) * (2 * n + a + b + 1)
                        / (2 * (n + 1) * (n + a + b + 1) * (2 * n + a + b));
            double Cn = (n + a) * (n + b) * (2 * n + a + b + 2)
                        / ((n + 1) * (n + a + b + 1) * (2 * n + a + b));
            int i2 = k % 3;
            prop_step_kernel<<<NN, 64>>>(coeffs, base + k,
                                         (float)An, (float)Bn, (float)Cn,
                                         i1, i0, i2, (k - 1) & 1, k & 1);
            i0 = i1; i1 = i2;
        }
        layer_epi_kernel<<<(NN * HID + 255) / 256, 256>>>();
    }

    // ---- output projection ----
    gemm2_kernel<<<(NN + 31) / 32, 256>>>(W2, b2, out);
}

// round 3
// speedup vs baseline: 2.0921x; 2.0921x over previous
#include <cuda_runtime.h>
#include <cuda_bf16.h>
#include <math.h>

// ---------------- problem constants (fixed by reference) ----------------
#define NN      100000      // N_NODES
#define NE      1600000     // N_EDGES
#define HID     64
#define INC     256
#define OUTC    32
#define KORD    10
#define NLAYERS 2
#define NBLK_SCAN 391       // ceil(NN/256)
#define NBLK_PROP 25000     // ceil(NN/4), 4 nodes (warps) per block

// ---------------- device scratch (static globals: allowed) --------------
__device__ int   g_is64;            // edge_index dtype flag (1 = int64, 0 = int32)
__device__ int   g_deg[NN];
__device__ float g_dinv[NN];        // 1/sqrt(deg+1)
__device__ float g_ds[NN];          // sqrt(deg+1)
__device__ int   g_off[NN + 1];
__device__ int   g_cur[NN];
__device__ int   g_src[NE];
__device__ int   g_bsum[512];

__device__ __align__(16) float g_G[2][NN * HID];  // pre-scaled (dinv * t) ping-pong
__device__ __align__(16) float g_OUT[NN * HID];   // per-layer accumulated output

// ======================= dtype detect + zero deg (fused) =======================
// If edge_index is int64 (LE, values < 2^31), every odd 32-bit word is 0.
__global__ void zero_detect_kernel(const int* __restrict__ ei32) {
    int i = blockIdx.x * 256 + threadIdx.x;
    if (i < NN) g_deg[i] = 0;
    if (blockIdx.x == 0) {
        __shared__ int nz;
        if (threadIdx.x == 0) nz = 0;
        __syncthreads();
        for (int t = threadIdx.x; t < 4096; t += 256)
            if (ei32[2 * t + 1] != 0) nz = 1;
        __syncthreads();
        if (threadIdx.x == 0) g_is64 = nz ? 0 : 1;
    }
}

__device__ __forceinline__ int edge_at(const void* __restrict__ ei, int idx, int is64) {
    if (is64) return (int)((const long long*)ei)[idx];
    return ((const int*)ei)[idx];
}

// ======================= CSR build =======================

__global__ void count_deg_kernel(const void* __restrict__ ei) {
    int is64 = g_is64;
    int e = blockIdx.x * 256 + threadIdx.x;
    if (e < NE) {
        int c = edge_at(ei, NE + e, is64);   // edge_index[1][e]
        atomicAdd(&g_deg[c], 1);
    }
}

// scan1 + dinv/ds fused (both consume g_deg)
__global__ void scan1_kernel() {
    __shared__ int sh[256];
    int tid = threadIdx.x;
    int i = blockIdx.x * 256 + tid;
    int v = (i < NN) ? g_deg[i] : 0;
    if (i < NN) {
        float d = (float)(v + 1);            // +1 self loop
        g_dinv[i] = rsqrtf(d);
        g_ds[i]   = sqrtf(d);
    }
    sh[tid] = v;
    __syncthreads();
#pragma unroll
    for (int o = 1; o < 256; o <<= 1) {
        int t = (tid >= o) ? sh[tid - o] : 0;
        __syncthreads();
        sh[tid] += t;
        __syncthreads();
    }
    if (i < NN) g_off[i] = sh[tid] - v;      // block-local exclusive
    if (tid == 255) g_bsum[blockIdx.x] = sh[255];
}

__global__ void scan2_kernel() {
    __shared__ int sh[512];
    int tid = threadIdx.x;
    int v = (tid < NBLK_SCAN) ? g_bsum[tid] : 0;
    sh[tid] = v;
    __syncthreads();
#pragma unroll
    for (int o = 1; o < 512; o <<= 1) {
        int t = (tid >= o) ? sh[tid - o] : 0;
        __syncthreads();
        sh[tid] += t;
        __syncthreads();
    }
    if (tid < NBLK_SCAN) g_bsum[tid] = sh[tid];    // inclusive block sums
}

__global__ void scan3_kernel() {
    int i = blockIdx.x * 256 + threadIdx.x;
    if (i < NN) {
        int add = (blockIdx.x > 0) ? g_bsum[blockIdx.x - 1] : 0;
        int o = g_off[i] + add;
        g_off[i] = o;
        g_cur[i] = o;
    }
    if (i == 0) g_off[NN] = NE;
}

__global__ void scatter_kernel(const void* __restrict__ ei) {
    int is64 = g_is64;
    int e = blockIdx.x * 256 + threadIdx.x;
    if (e < NE) {
        int r = edge_at(ei, e, is64);
        int c = edge_at(ei, NE + e, is64);
        int p = atomicAdd(&g_cur[c], 1);
        g_src[p] = r;
    }
}

// ======================= GEMM1: G0 = dinv * relu(x @ W1 + b1) =============
// 128x64 tile, 128 threads, 8x8 micro-tile, K-chunks of 16. ~1 LDS byte/FMA.

__global__ __launch_bounds__(128) void gemm1_kernel(const float* __restrict__ x,
                                                    const float* __restrict__ W1,
                                                    const float* __restrict__ b1) {
    __shared__ __align__(16) float xs[16][132];  // k-major, padded
    __shared__ __align__(16) float ws[16][64];
    int tid = threadIdx.x;
    int tx = tid & 7;          // col group (8 cols each)
    int ty = tid >> 3;         // row group (8 rows each), 0..15
    int row0 = blockIdx.x * 128;

    float acc[8][8];
#pragma unroll
    for (int i = 0; i < 8; i++)
#pragma unroll
        for (int j = 0; j < 8; j++) acc[i][j] = 0.f;

    for (int kc = 0; kc < INC; kc += 16) {
        // load x: thread tid owns global row row0+tid, 16 k-values as 4 float4
        {
            int gr = row0 + tid;
            float4 v[4];
            if (gr < NN) {
                const float4* xr = (const float4*)(x + gr * INC + kc);
#pragma unroll
                for (int q = 0; q < 4; q++) v[q] = xr[q];
            } else {
#pragma unroll
                for (int q = 0; q < 4; q++) v[q] = make_float4(0.f, 0.f, 0.f, 0.f);
            }
#pragma unroll
            for (int q = 0; q < 4; q++) {
                xs[q * 4 + 0][tid] = v[q].x;
                xs[q * 4 + 1][tid] = v[q].y;
                xs[q * 4 + 2][tid] = v[q].z;
                xs[q * 4 + 3][tid] = v[q].w;
            }
        }
        // load W1 chunk: thread covers row k=tid>>3, cols (tid&7)*8..+7
        {
            int k = tid >> 3, c = (tid & 7) * 8;
            const float4* wr = (const float4*)(W1 + (kc + k) * HID + c);
            *(float4*)&ws[k][c]     = wr[0];
            *(float4*)&ws[k][c + 4] = wr[1];
        }
        __syncthreads();
#pragma unroll
        for (int k = 0; k < 16; k++) {
            float4 xa = *(const float4*)&xs[k][ty * 8];
            float4 xb = *(const float4*)&xs[k][ty * 8 + 4];
            float4 wa = *(const float4*)&ws[k][tx * 8];
            float4 wb = *(const float4*)&ws[k][tx * 8 + 4];
            float xv[8] = {xa.x, xa.y, xa.z, xa.w, xb.x, xb.y, xb.z, xb.w};
            float wv[8] = {wa.x, wa.y, wa.z, wa.w, wb.x, wb.y, wb.z, wb.w};
#pragma unroll
            for (int i = 0; i < 8; i++)
#pragma unroll
                for (int j = 0; j < 8; j++) acc[i][j] += xv[i] * wv[j];
        }
        __syncthreads();
    }

#pragma unroll
    for (int i = 0; i < 8; i++) {
        int gr = row0 + ty * 8 + i;
        if (gr < NN) {
            float dv = g_dinv[gr];
#pragma unroll
            for (int j = 0; j < 8; j++) {
                int c = tx * 8 + j;
                float h = fmaxf(acc[i][j] + b1[c], 0.f);
                g_G[0][gr * HID + c] = dv * h;
            }
        }
    }
}

// ======================= Jacobi propagation (hot loop) ===================
// Warp per node, float2 per lane (full 256B row per warp). No T buffers:
// t1 = self*sqrt(d) (self-term already gathered), t0 = G_other*sqrt(d).

__global__ __launch_bounds__(128) void prop_first_kernel(const float* __restrict__ coeffs,
                                                         int base) {
    int w = threadIdx.x >> 5, lane = threadIdx.x & 31;
    int node = blockIdx.x * 4 + w;
    if (node >= NN) return;
    const float2* __restrict__ g = (const float2*)g_G[0];
    float2* __restrict__ go = (float2*)g_G[1];
    const int* __restrict__ src = g_src;

    int idx2 = node * 32 + lane;
    float2 self = g[idx2];
    float a0x = self.x, a0y = self.y;
    float a1x = 0.f, a1y = 0.f, a2x = 0.f, a2y = 0.f, a3x = 0.f, a3y = 0.f;
    int s = g_off[node], e = g_off[node + 1];
    int j = s;
    for (; j + 4 <= e; j += 4) {
        int s0 = src[j], s1 = src[j + 1], s2 = src[j + 2], s3 = src[j + 3];
        float2 v0 = g[s0 * 32 + lane];
        float2 v1 = g[s1 * 32 + lane];
        float2 v2 = g[s2 * 32 + lane];
        float2 v3 = g[s3 * 32 + lane];
        a0x += v0.x; a0y += v0.y;
        a1x += v1.x; a1y += v1.y;
        a2x += v2.x; a2y += v2.y;
        a3x += v3.x; a3y += v3.y;
    }
    for (; j < e; j++) {
        float2 v = g[src[j] * 32 + lane];
        a0x += v.x; a0y += v.y;
    }

    float dv = g_dinv[node], ds = g_ds[node];
    float t1x = dv * (a0x + a1x + a2x + a3x);
    float t1y = dv * (a0y + a1y + a2y + a3y);
    float t0x = self.x * ds, t0y = self.y * ds;   // h
    float c0 = coeffs[base], c1 = coeffs[base + 1];
    float2* OUT2 = (float2*)g_OUT;
    OUT2[idx2] = make_float2(c0 * t0x + c1 * t1x, c0 * t0y + c1 * t1y);
    go[idx2] = make_float2(dv * t1x, dv * t1y);
}

__global__ __launch_bounds__(128) void prop_step_kernel(const float* __restrict__ coeffs,
                                                        int base,
                                                        float An, float Bn, float Cn,
                                                        int igi) {
    int w = threadIdx.x >> 5, lane = threadIdx.x & 31;
    int node = blockIdx.x * 4 + w;
    if (node >= NN) return;
    const float2* __restrict__ g = (const float2*)g_G[igi];
    float2* __restrict__ go = (float2*)g_G[igi ^ 1];   // holds dinv*t0; overwritten with dinv*t2
    const int* __restrict__ src = g_src;

    int idx2 = node * 32 + lane;
    float2 self = g[idx2];                             // dinv*t1 at this node
    float a0x = self.x, a0y = self.y;
    float a1x = 0.f, a1y = 0.f, a2x = 0.f, a2y = 0.f, a3x = 0.f, a3y = 0.f;
    int s = g_off[node], e = g_off[node + 1];
    int j = s;
    for (; j + 4 <= e; j += 4) {
        int s0 = src[j], s1 = src[j + 1], s2 = src[j + 2], s3 = src[j + 3];
        float2 v0 = g[s0 * 32 + lane];
        float2 v1 = g[s1 * 32 + lane];
        float2 v2 = g[s2 * 32 + lane];
        float2 v3 = g[s3 * 32 + lane];
        a0x += v0.x; a0y += v0.y;
        a1x += v1.x; a1y += v1.y;
        a2x += v2.x; a2y += v2.y;
        a3x += v3.x; a3y += v3.y;
    }
    for (; j < e; j++) {
        float2 v = g[src[j] * 32 + lane];
        a0x += v.x; a0y += v.y;
    }

    float dv = g_dinv[node], ds = g_ds[node];
    float px = dv * (a0x + a1x + a2x + a3x);           // (P t1)
    float py = dv * (a0y + a1y + a2y + a3y);
    float t1x = self.x * ds, t1y = self.y * ds;
    float2 g0 = go[idx2];
    float t0x = g0.x * ds, t0y = g0.y * ds;
    float t2x = An * px + Bn * t1x - Cn * t0x;
    float t2y = An * py + Bn * t1y - Cn * t0y;
    float ck = coeffs[base];
    float2* OUT2 = (float2*)g_OUT;
    float2 o = OUT2[idx2];
    o.x += ck * t2x; o.y += ck * t2y;
    OUT2[idx2] = o;
    go[idx2] = make_float2(dv * t2x, dv * t2y);
}

// between layers: G0 = dinv * relu(OUT)  (OUT itself kept; relu applied on read)
__global__ void layer_epi_kernel() {
    int i = blockIdx.x * 256 + threadIdx.x;      // float2 index
    if (i < NN * 32) {
        const float2* OUT2 = (const float2*)g_OUT;
        float2* G02 = (float2*)g_G[0];
        float2 o = OUT2[i];
        float dv = g_dinv[i >> 5];
        G02[i] = make_float2(dv * fmaxf(o.x, 0.f), dv * fmaxf(o.y, 0.f));
    }
}

// ======================= GEMM2: out = relu(OUT) @ W2 + b2 ================
__global__ __launch_bounds__(256) void gemm2_kernel(const float* __restrict__ W2,
                                                    const float* __restrict__ b2,
                                                    float* __restrict__ out) {
    __shared__ __align__(16) float ws[64][32];
    __shared__ __align__(16) float xs[32][65];
    int tx = threadIdx.x & 31;   // col
    int ty = threadIdx.x >> 5;   // row group (0..7), 4 rows each
    int row0 = blockIdx.x * 32;

    for (int l = threadIdx.x; l < 64 * 32; l += 256) ws[l >> 5][l & 31] = W2[l];
    for (int l = threadIdx.x; l < 32 * 64; l += 256) {
        int r = l >> 6, k = l & 63;
        int gr = row0 + r;
        xs[r][k] = (gr < NN) ? fmaxf(g_OUT[gr * HID + k], 0.f) : 0.f;
    }
    __syncthreads();

    float acc[4] = {0.f, 0.f, 0.f, 0.f};
#pragma unroll
    for (int k = 0; k < 64; k++) {
        float wv = ws[k][tx];
#pragma unroll
        for (int i = 0; i < 4; i++) acc[i] += xs[ty * 4 + i][k] * wv;
    }
    float bb = b2[tx];
#pragma unroll
    for (int i = 0; i < 4; i++) {
        int gr = row0 + ty * 4 + i;
        if (gr < NN) out[gr * OUTC + tx] = acc[i] + bb;
    }
}

// ======================= launcher =======================

extern "C" void kernel_launch(void* const* d_in, const int* in_sizes, int n_in,
                              void* d_out, int out_size) {
    const float* x      = (const float*)d_in[0];
    const void*  ei     = d_in[1];                 // int32 or int64, detected on device
    const float* W1     = (const float*)d_in[2];
    const float* b1     = (const float*)d_in[3];
    const float* coeffs = (const float*)d_in[4];
    const float* W2     = (const float*)d_in[5];
    const float* b2     = (const float*)d_in[6];
    float*       out    = (float*)d_out;

    // ---- detect edge dtype + build norm + CSR ----
    zero_detect_kernel<<<NBLK_SCAN, 256>>>((const int*)ei);
    count_deg_kernel<<<NE / 256, 256>>>(ei);
    scan1_kernel<<<NBLK_SCAN, 256>>>();
    scan2_kernel<<<1, 512>>>();
    scan3_kernel<<<NBLK_SCAN, 256>>>();
    scatter_kernel<<<NE / 256, 256>>>(ei);

    // ---- input projection ----
    gemm1_kernel<<<(NN + 127) / 128, 128>>>(x, W1, b1);

    // ---- Jacobi layers ----
    const double a = 0.5, b = 0.5;
    for (int l = 0; l < NLAYERS; l++) {
        int base = l * (KORD + 1);
        prop_first_kernel<<<NBLK_PROP, 128>>>(coeffs, base);
        for (int k = 2; k <= KORD; k++) {
            double n = (double)(k - 1);
            double An = (2 * n + a + b + 1) * (2 * n + a + b + 2)
                        / (2 * (n + 1) * (n + a + b + 1));
            double Bn = (a * a - b * b) * (2 * n + a + b + 1)
                        / (2 * (n + 1) * (n + a + b + 1) * (2 * n + a + b));
            double Cn = (n + a) * (n + b) * (2 * n + a + b + 2)
                        / ((n + 1) * (n + a + b + 1) * (2 * n + a + b));
            prop_step_kernel<<<NBLK_PROP, 128>>>(coeffs, base + k,
                                                 (float)An, (float)Bn, (float)Cn,
                                                 (k - 1) & 1);
        }
        layer_epi_kernel<<<(NN * 32 + 255) / 256, 256>>>();
    }

    // ---- output projection ----
    gemm2_kernel<<<(NN + 31) / 32, 256>>>(W2, b2, out);
}

// round 5
// speedup vs baseline: 2.1702x; 1.0373x over previous
#include <cuda_runtime.h>
#include <cuda_fp16.h>
#include <cstdint>
#include <math.h>

// ---------------- problem constants (fixed by reference) ----------------
#define NN      100000      // N_NODES
#define NE      1600000     // N_EDGES
#define HID     64
#define INC     256
#define OUTC    32
#define KORD    10
#define NLAYERS 2
#define NBLK_SCAN 391       // ceil(NN/256)
#define NBLK_PROP 25000     // ceil(NN/4), 4 nodes (warps) per block

// ---------------- device scratch (static globals: allowed) --------------
__device__ int   g_is64;            // edge_index dtype flag (1 = int64, 0 = int32)
__device__ int   g_deg[NN];
__device__ float g_dinv[NN];        // 1/sqrt(deg+1)
__device__ float g_ds[NN];          // sqrt(deg+1)
__device__ int   g_off[NN + 1];
__device__ int   g_cur[NN];
__device__ int   g_src[NE];
__device__ int   g_bsum[512];

// slot k holds dinv * t_k  (slot0 = dinv * h).  282 MB static, zero-init bss.
__device__ __align__(16) float g_S[KORD + 1][NN * HID];

// ======================= dtype detect + zero deg (fused) =======================
__global__ void zero_detect_kernel(const int* __restrict__ ei32) {
    int i = blockIdx.x * 256 + threadIdx.x;
    if (i < NN) g_deg[i] = 0;
    if (blockIdx.x == 0) {
        __shared__ int nz;
        if (threadIdx.x == 0) nz = 0;
        __syncthreads();
        for (int t = threadIdx.x; t < 4096; t += 256)
            if (ei32[2 * t + 1] != 0) nz = 1;
        __syncthreads();
        if (threadIdx.x == 0) g_is64 = nz ? 0 : 1;
    }
}

__device__ __forceinline__ int edge_at(const void* __restrict__ ei, int idx, int is64) {
    if (is64) return (int)((const long long*)ei)[idx];
    return ((const int*)ei)[idx];
}

// ======================= CSR build =======================

__global__ void count_deg_kernel(const void* __restrict__ ei) {
    int is64 = g_is64;
    int e = blockIdx.x * 256 + threadIdx.x;
    if (e < NE) {
        int c = edge_at(ei, NE + e, is64);
        atomicAdd(&g_deg[c], 1);
    }
}

// scan1 + dinv/ds fused
__global__ void scan1_kernel() {
    __shared__ int sh[256];
    int tid = threadIdx.x;
    int i = blockIdx.x * 256 + tid;
    int v = (i < NN) ? g_deg[i] : 0;
    if (i < NN) {
        float d = (float)(v + 1);
        g_dinv[i] = rsqrtf(d);
        g_ds[i]   = sqrtf(d);
    }
    sh[tid] = v;
    __syncthreads();
#pragma unroll
    for (int o = 1; o < 256; o <<= 1) {
        int t = (tid >= o) ? sh[tid - o] : 0;
        __syncthreads();
        sh[tid] += t;
        __syncthreads();
    }
    if (i < NN) g_off[i] = sh[tid] - v;
    if (tid == 255) g_bsum[blockIdx.x] = sh[255];
}

// merged scan2+scan3: each block redundantly scans the 391 block sums in smem,
// then applies prefix to its own 512 offsets.
__global__ void scan23_kernel() {
    __shared__ int sh[512];
    int tid = threadIdx.x;                       // 512 threads
    int v = (tid < NBLK_SCAN) ? g_bsum[tid] : 0;
    sh[tid] = v;
    __syncthreads();
#pragma unroll
    for (int o = 1; o < 512; o <<= 1) {
        int t = (tid >= o) ? sh[tid - o] : 0;
        __syncthreads();
        sh[tid] += t;
        __syncthreads();
    }
    int i = blockIdx.x * 512 + tid;
    if (i < NN) {
        int sb = i >> 8;                         // scan1 block of i
        int add = (sb > 0) ? sh[sb - 1] : 0;
        int o = g_off[i] + add;
        g_off[i] = o;
        g_cur[i] = o;
    }
    if (i == 0) g_off[NN] = NE;
}

__global__ void scatter_kernel(const void* __restrict__ ei) {
    int is64 = g_is64;
    int e = blockIdx.x * 256 + threadIdx.x;
    if (e < NE) {
        int r = edge_at(ei, e, is64);
        int c = edge_at(ei, NE + e, is64);
        int p = atomicAdd(&g_cur[c], 1);
        g_src[p] = r;
    }
}

// ======================= GEMM1 (tensor cores, fp16 in / fp32 acc) ========
// slot0 = dinv * relu(x @ W1 + b1).  Block: 128 thr (4 warps), 64x64 tile,
// K chunks of 32, mma.m16n8k16. Each warp: rows 16w..16w+15, all 64 cols.

#define KC 32

__global__ __launch_bounds__(128) void gemm1_kernel(const float* __restrict__ x,
                                                    const float* __restrict__ W1,
                                                    const float* __restrict__ b1) {
    __shared__ __align__(16) __half As[64][KC + 8];   // [m][k], padded
    __shared__ __align__(16) __half Bs[64][KC + 8];   // [n][k], padded
    __shared__ float bsh[64];
    int tid = threadIdx.x;
    int warp = tid >> 5, lane = tid & 31;
    int g = lane >> 2;              // 0..7
    int t2 = (lane & 3) * 2;        // 0,2,4,6
    int row0 = blockIdx.x * 64;

    if (tid < 64) bsh[tid] = b1[tid];

    float acc[8][4];
#pragma unroll
    for (int nt = 0; nt < 8; nt++)
#pragma unroll
        for (int q = 0; q < 4; q++) acc[nt][q] = 0.f;

    for (int kc = 0; kc < INC; kc += KC) {
        // ---- load x tile: 64 rows x 32 k. thread: row=tid>>1, 16 floats.
        {
            int r = tid >> 1;
            int kp = (tid & 1) * 16;
            int gr = row0 + r;
            const float4* xr = (const float4*)(x + (long long)gr * INC + kc + kp);
            float4 v[4];
#pragma unroll
            for (int q = 0; q < 4; q++)
                v[q] = (gr < NN) ? xr[q] : make_float4(0.f, 0.f, 0.f, 0.f);
            __half2* dst = (__half2*)&As[r][kp];
#pragma unroll
            for (int q = 0; q < 4; q++) {
                dst[q * 2 + 0] = __floats2half2_rn(v[q].x, v[q].y);
                dst[q * 2 + 1] = __floats2half2_rn(v[q].z, v[q].w);
            }
        }
        // ---- load W1 chunk: 32 k x 64 n -> Bs[n][k]
        for (int q = 0; q < 4; q++) {
            int idx = tid + 128 * q;              // 0..511 float4s
            int k = idx >> 4;
            int n0 = (idx & 15) * 4;
            float4 wv = *(const float4*)(W1 + (long long)(kc + k) * HID + n0);
            Bs[n0 + 0][k] = __float2half_rn(wv.x);
            Bs[n0 + 1][k] = __float2half_rn(wv.y);
            Bs[n0 + 2][k] = __float2half_rn(wv.z);
            Bs[n0 + 3][k] = __float2half_rn(wv.w);
        }
        __syncthreads();

#pragma unroll
        for (int kk = 0; kk < KC; kk += 16) {
            uint32_t a0 = *(const uint32_t*)&As[16 * warp + g    ][kk + t2];
            uint32_t a1 = *(const uint32_t*)&As[16 * warp + g + 8][kk + t2];
            uint32_t a2 = *(const uint32_t*)&As[16 * warp + g    ][kk + t2 + 8];
            uint32_t a3 = *(const uint32_t*)&As[16 * warp + g + 8][kk + t2 + 8];
#pragma unroll
            for (int nt = 0; nt < 8; nt++) {
                uint32_t b0 = *(const uint32_t*)&Bs[nt * 8 + g][kk + t2];
                uint32_t b1f = *(const uint32_t*)&Bs[nt * 8 + g][kk + t2 + 8];
                asm volatile(
                    "mma.sync.aligned.m16n8k16.row.col.f32.f16.f16.f32 "
                    "{%0,%1,%2,%3}, {%4,%5,%6,%7}, {%8,%9}, {%0,%1,%2,%3};"
                    : "+f"(acc[nt][0]), "+f"(acc[nt][1]),
                      "+f"(acc[nt][2]), "+f"(acc[nt][3])
                    : "r"(a0), "r"(a1), "r"(a2), "r"(a3), "r"(b0), "r"(b1f));
            }
        }
        __syncthreads();
    }

    // epilogue: D[g][t2],D[g][t2+1] ; D[g+8][t2],D[g+8][t2+1] per n-tile
    int r1 = row0 + 16 * warp + g;
    int r2 = r1 + 8;
    float dv1 = (r1 < NN) ? g_dinv[r1] : 0.f;
    float dv2 = (r2 < NN) ? g_dinv[r2] : 0.f;
#pragma unroll
    for (int nt = 0; nt < 8; nt++) {
        int c0 = nt * 8 + t2;
        float bb0 = bsh[c0], bb1 = bsh[c0 + 1];
        if (r1 < NN) {
            float h0 = fmaxf(acc[nt][0] + bb0, 0.f);
            float h1 = fmaxf(acc[nt][1] + bb1, 0.f);
            *(float2*)&g_S[0][(long long)r1 * HID + c0] = make_float2(dv1 * h0, dv1 * h1);
        }
        if (r2 < NN) {
            float h0 = fmaxf(acc[nt][2] + bb0, 0.f);
            float h1 = fmaxf(acc[nt][3] + bb1, 0.f);
            *(float2*)&g_S[0][(long long)r2 * HID + c0] = make_float2(dv2 * h0, dv2 * h1);
        }
    }
}

// ======================= Jacobi propagation (hot loop) ===================
// Warp per node, float2 per lane. slot[kin] gathered; slot[kt0] gives t0;
// writes slot[kout] = dinv * t2. No OUT accumulation in the hot loop.

__global__ __launch_bounds__(128) void prop_first_kernel() {
    int w = threadIdx.x >> 5, lane = threadIdx.x & 31;
    int node = blockIdx.x * 4 + w;
    if (node >= NN) return;
    const float2* __restrict__ g = (const float2*)g_S[0];
    float2* __restrict__ go = (float2*)g_S[1];
    const int* __restrict__ src = g_src;

    int idx2 = node * 32 + lane;
    float2 self = g[idx2];
    float a0x = self.x, a0y = self.y;
    float a1x = 0.f, a1y = 0.f, a2x = 0.f, a2y = 0.f, a3x = 0.f, a3y = 0.f;
    int s = g_off[node], e = g_off[node + 1];
    int j = s;
    for (; j + 4 <= e; j += 4) {
        int s0 = src[j], s1 = src[j + 1], s2 = src[j + 2], s3 = src[j + 3];
        float2 v0 = g[s0 * 32 + lane];
        float2 v1 = g[s1 * 32 + lane];
        float2 v2 = g[s2 * 32 + lane];
        float2 v3 = g[s3 * 32 + lane];
        a0x += v0.x; a0y += v0.y;
        a1x += v1.x; a1y += v1.y;
        a2x += v2.x; a2y += v2.y;
        a3x += v3.x; a3y += v3.y;
    }
    for (; j < e; j++) {
        float2 v = g[src[j] * 32 + lane];
        a0x += v.x; a0y += v.y;
    }
    float dv = g_dinv[node];
    // slot1 = dinv * t1 = dinv * dinv * (sum of gathered dinv*h)
    go[idx2] = make_float2(dv * dv * (a0x + a1x + a2x + a3x),
                           dv * dv * (a0y + a1y + a2y + a3y));
}

__global__ __launch_bounds__(128) void prop_step_kernel(float An, float Bn, float Cn,
                                                        int kin, int kt0, int kout) {
    int w = threadIdx.x >> 5, lane = threadIdx.x & 31;
    int node = blockIdx.x * 4 + w;
    if (node >= NN) return;
    const float2* __restrict__ g = (const float2*)g_S[kin];
    const float2* __restrict__ gt0 = (const float2*)g_S[kt0];
    float2* __restrict__ go = (float2*)g_S[kout];
    const int* __restrict__ src = g_src;

    int idx2 = node * 32 + lane;
    float2 self = g[idx2];                       // dinv * t1
    float a0x = self.x, a0y = self.y;
    float a1x = 0.f, a1y = 0.f, a2x = 0.f, a2y = 0.f, a3x = 0.f, a3y = 0.f;
    int s = g_off[node], e = g_off[node + 1];
    int j = s;
    for (; j + 4 <= e; j += 4) {
        int s0 = src[j], s1 = src[j + 1], s2 = src[j + 2], s3 = src[j + 3];
        float2 v0 = g[s0 * 32 + lane];
        float2 v1 = g[s1 * 32 + lane];
        float2 v2 = g[s2 * 32 + lane];
        float2 v3 = g[s3 * 32 + lane];
        a0x += v0.x; a0y += v0.y;
        a1x += v1.x; a1y += v1.y;
        a2x += v2.x; a2y += v2.y;
        a3x += v3.x; a3y += v3.y;
    }
    for (; j < e; j++) {
        float2 v = g[src[j] * 32 + lane];
        a0x += v.x; a0y += v.y;
    }

    float dv = g_dinv[node], ds = g_ds[node];
    float px = dv * (a0x + a1x + a2x + a3x);     // (P t1)
    float py = dv * (a0y + a1y + a2y + a3y);
    float t1x = self.x * ds, t1y = self.y * ds;
    float2 g0 = gt0[idx2];
    float t0x = g0.x * ds, t0y = g0.y * ds;
    float t2x = An * px + Bn * t1x - Cn * t0x;
    float t2y = An * py + Bn * t1y - Cn * t0y;
    go[idx2] = make_float2(dv * t2x, dv * t2y);
}

// ======================= layer epilogue ==================================
// slot0' = dinv * relu(sum_k c_k t_k) = relu(sum_k c_k slot_k)   (dinv>0)
__global__ void layer_epi_kernel(const float* __restrict__ coeffs, int base) {
    int i = blockIdx.x * 256 + threadIdx.x;      // float4 index
    if (i >= NN * (HID / 4)) return;
    float c[KORD + 1];
#pragma unroll
    for (int k = 0; k <= KORD; k++) c[k] = coeffs[base + k];
    float4 acc = make_float4(0.f, 0.f, 0.f, 0.f);
#pragma unroll
    for (int k = 0; k <= KORD; k++) {
        float4 v = *(const float4*)&g_S[k][i * 4];
        acc.x += c[k] * v.x; acc.y += c[k] * v.y;
        acc.z += c[k] * v.z; acc.w += c[k] * v.w;
    }
    acc.x = fmaxf(acc.x, 0.f); acc.y = fmaxf(acc.y, 0.f);
    acc.z = fmaxf(acc.z, 0.f); acc.w = fmaxf(acc.w, 0.f);
    *(float4*)&g_S[0][i * 4] = acc;
}

// ======================= GEMM2: out = (ds*slot0) @ W2 + b2 ===============
__global__ __launch_bounds__(256) void gemm2_kernel(const float* __restrict__ W2,
                                                    const float* __restrict__ b2,
                                                    float* __restrict__ out) {
    __shared__ __align__(16) float ws[64][32];
    __shared__ __align__(16) float xs[32][65];
    int tx = threadIdx.x & 31;
    int ty = threadIdx.x >> 5;
    int row0 = blockIdx.x * 32;

    for (int l = threadIdx.x; l < 64 * 32; l += 256) ws[l >> 5][l & 31] = W2[l];
    for (int l = threadIdx.x; l < 32 * 64; l += 256) {
        int r = l >> 6, k = l & 63;
        int gr = row0 + r;
        xs[r][k] = (gr < NN) ? g_ds[gr] * g_S[0][(long long)gr * HID + k] : 0.f;
    }
    __syncthreads();

    float acc[4] = {0.f, 0.f, 0.f, 0.f};
#pragma unroll
    for (int k = 0; k < 64; k++) {
        float wv = ws[k][tx];
#pragma unroll
        for (int i = 0; i < 4; i++) acc[i] += xs[ty * 4 + i][k] * wv;
    }
    float bb = b2[tx];
#pragma unroll
    for (int i = 0; i < 4; i++) {
        int gr = row0 + ty * 4 + i;
        if (gr < NN) out[gr * OUTC + tx] = acc[i] + bb;
    }
}

// ======================= launcher =======================

extern "C" void kernel_launch(void* const* d_in, const int* in_sizes, int n_in,
                              void* d_out, int out_size) {
    const float* x      = (const float*)d_in[0];
    const void*  ei     = d_in[1];
    const float* W1     = (const float*)d_in[2];
    const float* b1     = (const float*)d_in[3];
    const float* coeffs = (const float*)d_in[4];
    const float* W2     = (const float*)d_in[5];
    const float* b2     = (const float*)d_in[6];
    float*       out    = (float*)d_out;

    zero_detect_kernel<<<NBLK_SCAN, 256>>>((const int*)ei);
    count_deg_kernel<<<NE / 256, 256>>>(ei);
    scan1_kernel<<<NBLK_SCAN, 256>>>();
    scan23_kernel<<<(NN + 511) / 512, 512>>>();
    scatter_kernel<<<NE / 256, 256>>>(ei);

    gemm1_kernel<<<(NN + 63) / 64, 128>>>(x, W1, b1);

    const double a = 0.5, b = 0.5;
    for (int l = 0; l < NLAYERS; l++) {
        prop_first_kernel<<<NBLK_PROP, 128>>>();
        for (int k = 2; k <= KORD; k++) {
            double n = (double)(k - 1);
            double An = (2 * n + a + b + 1) * (2 * n + a + b + 2)
                        / (2 * (n + 1) * (n + a + b + 1));
            double Bn = (a * a - b * b) * (2 * n + a + b + 1)
                        / (2 * (n + 1) * (n + a + b + 1) * (2 * n + a + b));
            double Cn = (n + a) * (n + b) * (2 * n + a + b + 2)
                        / ((n + 1) * (n + a + b + 1) * (2 * n + a + b));
            prop_step_kernel<<<NBLK_PROP, 128>>>((float)An, (float)Bn, (float)Cn,
                                                 k - 1, k - 2, k);
        }
        layer_epi_kernel<<<(NN * (HID / 4) + 255) / 256, 256>>>(coeffs, l * (KORD + 1));
    }

    gemm2_kernel<<<(NN + 31) / 32, 256>>>(W2, b2, out);
}

// round 6
// speedup vs baseline: 2.3580x; 1.0865x over previous
#include <cuda_runtime.h>
#include <cuda_fp16.h>
#include <cstdint>
#include <math.h>

// ---------------- problem constants (fixed by reference) ----------------
#define NN      100000      // N_NODES
#define NE      1600000     // N_EDGES
#define HID     64
#define INC     256
#define OUTC    32
#define KORD    10
#define NLAYERS 2
#define NBLK_SCAN 391       // ceil(NN/256)
#define NBLK_PROP 25000     // ceil(NN/4), 4 nodes (warps) per block

// ---------------- device scratch (static globals: allowed) --------------
__device__ int   g_is64;
__device__ int   g_deg[NN];
__device__ float g_dinv[NN];        // 1/sqrt(deg+1)
__device__ float g_ds[NN];          // sqrt(deg+1)
__device__ int   g_off[NN + 1];
__device__ int   g_cur[NN];
__device__ int   g_src[NE];
__device__ int   g_bsum[512];

// slot k holds dinv * t_k as half2 (32 half2 = 64 ch per node). 141 MB bss.
__device__ __align__(16) __half2 g_H[KORD + 1][NN * 32];

// ======================= dtype detect + zero deg (fused) ================
__global__ void zero_detect_kernel(const int* __restrict__ ei32) {
    int i = blockIdx.x * 256 + threadIdx.x;
    if (i < NN) g_deg[i] = 0;
    if (blockIdx.x == 0) {
        __shared__ int nz;
        if (threadIdx.x == 0) nz = 0;
        __syncthreads();
        for (int t = threadIdx.x; t < 4096; t += 256)
            if (ei32[2 * t + 1] != 0) nz = 1;
        __syncthreads();
        if (threadIdx.x == 0) g_is64 = nz ? 0 : 1;
    }
}

__device__ __forceinline__ int edge_at(const void* __restrict__ ei, int idx, int is64) {
    if (is64) return (int)((const long long*)ei)[idx];
    return ((const int*)ei)[idx];
}

// ======================= CSR build =======================

__global__ void count_deg_kernel(const void* __restrict__ ei) {
    int is64 = g_is64;
    int e = blockIdx.x * 256 + threadIdx.x;
    if (e < NE) {
        int c = edge_at(ei, NE + e, is64);
        atomicAdd(&g_deg[c], 1);
    }
}

__global__ void scan1_kernel() {
    __shared__ int sh[256];
    int tid = threadIdx.x;
    int i = blockIdx.x * 256 + tid;
    int v = (i < NN) ? g_deg[i] : 0;
    if (i < NN) {
        float d = (float)(v + 1);
        g_dinv[i] = rsqrtf(d);
        g_ds[i]   = sqrtf(d);
    }
    sh[tid] = v;
    __syncthreads();
#pragma unroll
    for (int o = 1; o < 256; o <<= 1) {
        int t = (tid >= o) ? sh[tid - o] : 0;
        __syncthreads();
        sh[tid] += t;
        __syncthreads();
    }
    if (i < NN) g_off[i] = sh[tid] - v;
    if (tid == 255) g_bsum[blockIdx.x] = sh[255];
}

__global__ void scan23_kernel() {
    __shared__ int sh[512];
    int tid = threadIdx.x;
    int v = (tid < NBLK_SCAN) ? g_bsum[tid] : 0;
    sh[tid] = v;
    __syncthreads();
#pragma unroll
    for (int o = 1; o < 512; o <<= 1) {
        int t = (tid >= o) ? sh[tid - o] : 0;
        __syncthreads();
        sh[tid] += t;
        __syncthreads();
    }
    int i = blockIdx.x * 512 + tid;
    if (i < NN) {
        int sb = i >> 8;
        int add = (sb > 0) ? sh[sb - 1] : 0;
        int o = g_off[i] + add;
        g_off[i] = o;
        g_cur[i] = o;
    }
    if (i == 0) g_off[NN] = NE;
}

__global__ void scatter_kernel(const void* __restrict__ ei) {
    int is64 = g_is64;
    int e = blockIdx.x * 256 + threadIdx.x;
    if (e < NE) {
        int r = edge_at(ei, e, is64);
        int c = edge_at(ei, NE + e, is64);
        int p = atomicAdd(&g_cur[c], 1);
        g_src[p] = r;
    }
}

// ======================= GEMM1 (tensor cores, fp16 in / fp32 acc) ========
// g_H[0] = half(dinv * relu(x @ W1 + b1)).

#define KC 32

__global__ __launch_bounds__(128) void gemm1_kernel(const float* __restrict__ x,
                                                    const float* __restrict__ W1,
                                                    const float* __restrict__ b1) {
    __shared__ __align__(16) __half As[64][KC + 8];
    __shared__ __align__(16) __half Bs[64][KC + 8];
    __shared__ float bsh[64];
    int tid = threadIdx.x;
    int warp = tid >> 5, lane = tid & 31;
    int g = lane >> 2;
    int t2 = (lane & 3) * 2;
    int row0 = blockIdx.x * 64;

    if (tid < 64) bsh[tid] = b1[tid];

    float acc[8][4];
#pragma unroll
    for (int nt = 0; nt < 8; nt++)
#pragma unroll
        for (int q = 0; q < 4; q++) acc[nt][q] = 0.f;

    for (int kc = 0; kc < INC; kc += KC) {
        {
            int r = tid >> 1;
            int kp = (tid & 1) * 16;
            int gr = row0 + r;
            const float4* xr = (const float4*)(x + (long long)gr * INC + kc + kp);
            float4 v[4];
#pragma unroll
            for (int q = 0; q < 4; q++)
                v[q] = (gr < NN) ? xr[q] : make_float4(0.f, 0.f, 0.f, 0.f);
            __half2* dst = (__half2*)&As[r][kp];
#pragma unroll
            for (int q = 0; q < 4; q++) {
                dst[q * 2 + 0] = __floats2half2_rn(v[q].x, v[q].y);
                dst[q * 2 + 1] = __floats2half2_rn(v[q].z, v[q].w);
            }
        }
        for (int q = 0; q < 4; q++) {
            int idx = tid + 128 * q;
            int k = idx >> 4;
            int n0 = (idx & 15) * 4;
            float4 wv = *(const float4*)(W1 + (long long)(kc + k) * HID + n0);
            Bs[n0 + 0][k] = __float2half_rn(wv.x);
            Bs[n0 + 1][k] = __float2half_rn(wv.y);
            Bs[n0 + 2][k] = __float2half_rn(wv.z);
            Bs[n0 + 3][k] = __float2half_rn(wv.w);
        }
        __syncthreads();

#pragma unroll
        for (int kk = 0; kk < KC; kk += 16) {
            uint32_t a0 = *(const uint32_t*)&As[16 * warp + g    ][kk + t2];
            uint32_t a1 = *(const uint32_t*)&As[16 * warp + g + 8][kk + t2];
            uint32_t a2 = *(const uint32_t*)&As[16 * warp + g    ][kk + t2 + 8];
            uint32_t a3 = *(const uint32_t*)&As[16 * warp + g + 8][kk + t2 + 8];
#pragma unroll
            for (int nt = 0; nt < 8; nt++) {
                uint32_t b0 = *(const uint32_t*)&Bs[nt * 8 + g][kk + t2];
                uint32_t b1f = *(const uint32_t*)&Bs[nt * 8 + g][kk + t2 + 8];
                asm volatile(
                    "mma.sync.aligned.m16n8k16.row.col.f32.f16.f16.f32 "
                    "{%0,%1,%2,%3}, {%4,%5,%6,%7}, {%8,%9}, {%0,%1,%2,%3};"
                    : "+f"(acc[nt][0]), "+f"(acc[nt][1]),
                      "+f"(acc[nt][2]), "+f"(acc[nt][3])
                    : "r"(a0), "r"(a1), "r"(a2), "r"(a3), "r"(b0), "r"(b1f));
            }
        }
        __syncthreads();
    }

    int r1 = row0 + 16 * warp + g;
    int r2 = r1 + 8;
    float dv1 = (r1 < NN) ? g_dinv[r1] : 0.f;
    float dv2 = (r2 < NN) ? g_dinv[r2] : 0.f;
#pragma unroll
    for (int nt = 0; nt < 8; nt++) {
        int c0 = nt * 8 + t2;
        float bb0 = bsh[c0], bb1 = bsh[c0 + 1];
        if (r1 < NN) {
            float h0 = fmaxf(acc[nt][0] + bb0, 0.f);
            float h1 = fmaxf(acc[nt][1] + bb1, 0.f);
            g_H[0][r1 * 32 + (c0 >> 1)] = __floats2half2_rn(dv1 * h0, dv1 * h1);
        }
        if (r2 < NN) {
            float h0 = fmaxf(acc[nt][2] + bb0, 0.f);
            float h1 = fmaxf(acc[nt][3] + bb1, 0.f);
            g_H[0][r2 * 32 + (c0 >> 1)] = __floats2half2_rn(dv2 * h0, dv2 * h1);
        }
    }
}

// ======================= Jacobi propagation (hot loop) ===================
// Warp per node, one half2 (2 ch) per lane = 128B row per warp.

__global__ __launch_bounds__(128) void prop_first_kernel() {
    int w = threadIdx.x >> 5, lane = threadIdx.x & 31;
    int node = blockIdx.x * 4 + w;
    if (node >= NN) return;
    const __half2* __restrict__ g = g_H[0];
    __half2* __restrict__ go = g_H[1];
    const int* __restrict__ src = g_src;

    int idx2 = node * 32 + lane;
    float2 self = __half22float2(g[idx2]);      // includes self loop
    float a0x = self.x, a0y = self.y;
    float a1x = 0.f, a1y = 0.f, a2x = 0.f, a2y = 0.f, a3x = 0.f, a3y = 0.f;
    int s = g_off[node], e = g_off[node + 1];
    int j = s;
    for (; j + 4 <= e; j += 4) {
        int s0 = src[j], s1 = src[j + 1], s2 = src[j + 2], s3 = src[j + 3];
        float2 v0 = __half22float2(g[s0 * 32 + lane]);
        float2 v1 = __half22float2(g[s1 * 32 + lane]);
        float2 v2 = __half22float2(g[s2 * 32 + lane]);
        float2 v3 = __half22float2(g[s3 * 32 + lane]);
        a0x += v0.x; a0y += v0.y;
        a1x += v1.x; a1y += v1.y;
        a2x += v2.x; a2y += v2.y;
        a3x += v3.x; a3y += v3.y;
    }
    for (; j < e; j++) {
        float2 v = __half22float2(g[src[j] * 32 + lane]);
        a0x += v.x; a0y += v.y;
    }
    float dv = g_dinv[node];
    float dv2f = dv * dv;
    go[idx2] = __floats2half2_rn(dv2f * (a0x + a1x + a2x + a3x),
                                 dv2f * (a0y + a1y + a2y + a3y));
}

__global__ __launch_bounds__(128) void prop_step_kernel(float An, float Bn, float Cn,
                                                        int kin, int kt0, int kout) {
    int w = threadIdx.x >> 5, lane = threadIdx.x & 31;
    int node = blockIdx.x * 4 + w;
    if (node >= NN) return;
    const __half2* __restrict__ g = g_H[kin];
    const __half2* __restrict__ gt0 = g_H[kt0];
    __half2* __restrict__ go = g_H[kout];
    const int* __restrict__ src = g_src;

    int idx2 = node * 32 + lane;
    float2 self = __half22float2(g[idx2]);      // dinv * t1
    float a0x = self.x, a0y = self.y;
    float a1x = 0.f, a1y = 0.f, a2x = 0.f, a2y = 0.f, a3x = 0.f, a3y = 0.f;
    int s = g_off[node], e = g_off[node + 1];
    int j = s;
    for (; j + 4 <= e; j += 4) {
        int s0 = src[j], s1 = src[j + 1], s2 = src[j + 2], s3 = src[j + 3];
        float2 v0 = __half22float2(g[s0 * 32 + lane]);
        float2 v1 = __half22float2(g[s1 * 32 + lane]);
        float2 v2 = __half22float2(g[s2 * 32 + lane]);
        float2 v3 = __half22float2(g[s3 * 32 + lane]);
        a0x += v0.x; a0y += v0.y;
        a1x += v1.x; a1y += v1.y;
        a2x += v2.x; a2y += v2.y;
        a3x += v3.x; a3y += v3.y;
    }
    for (; j < e; j++) {
        float2 v = __half22float2(g[src[j] * 32 + lane]);
        a0x += v.x; a0y += v.y;
    }

    float dv = g_dinv[node], ds = g_ds[node];
    float px = dv * (a0x + a1x + a2x + a3x);
    float py = dv * (a0y + a1y + a2y + a3y);
    float t1x = self.x * ds, t1y = self.y * ds;
    float2 g0 = __half22float2(gt0[idx2]);
    float t0x = g0.x * ds, t0y = g0.y * ds;
    float t2x = An * px + Bn * t1x - Cn * t0x;
    float t2y = An * py + Bn * t1y - Cn * t0y;
    go[idx2] = __floats2half2_rn(dv * t2x, dv * t2y);
}

// ======================= layer epilogue ==================================
// slot0' = relu(sum_k c_k slot_k)  (= dinv * relu(sum c_k t_k), dinv>0)
__global__ void layer_epi_kernel(const float* __restrict__ coeffs, int base) {
    int i = blockIdx.x * 256 + threadIdx.x;     // half2 index
    if (i >= NN * 32) return;
    float c[KORD + 1];
#pragma unroll
    for (int k = 0; k <= KORD; k++) c[k] = coeffs[base + k];
    float ax = 0.f, ay = 0.f;
#pragma unroll
    for (int k = 0; k <= KORD; k++) {
        float2 v = __half22float2(g_H[k][i]);
        ax += c[k] * v.x;
        ay += c[k] * v.y;
    }
    g_H[0][i] = __floats2half2_rn(fmaxf(ax, 0.f), fmaxf(ay, 0.f));
}

// ======================= GEMM2: out = (ds*slot0) @ W2 + b2 ===============
__global__ __launch_bounds__(256) void gemm2_kernel(const float* __restrict__ W2,
                                                    const float* __restrict__ b2,
                                                    float* __restrict__ out) {
    __shared__ __align__(16) float ws[64][32];
    __shared__ __align__(16) float xs[32][65];
    int tx = threadIdx.x & 31;
    int ty = threadIdx.x >> 5;
    int row0 = blockIdx.x * 32;

    for (int l = threadIdx.x; l < 64 * 32; l += 256) ws[l >> 5][l & 31] = W2[l];
    for (int l = threadIdx.x; l < 32 * 32; l += 256) {   // 32 rows x 32 half2
        int r = l >> 5, kk = l & 31;
        int gr = row0 + r;
        float2 v = (gr < NN) ? __half22float2(g_H[0][gr * 32 + kk])
                             : make_float2(0.f, 0.f);
        float dsv = (gr < NN) ? g_ds[gr] : 0.f;
        xs[r][kk * 2]     = dsv * v.x;
        xs[r][kk * 2 + 1] = dsv * v.y;
    }
    __syncthreads();

    float acc[4] = {0.f, 0.f, 0.f, 0.f};
#pragma unroll
    for (int k = 0; k < 64; k++) {
        float wv = ws[k][tx];
#pragma unroll
        for (int i = 0; i < 4; i++) acc[i] += xs[ty * 4 + i][k] * wv;
    }
    float bb = b2[tx];
#pragma unroll
    for (int i = 0; i < 4; i++) {
        int gr = row0 + ty * 4 + i;
        if (gr < NN) out[gr * OUTC + tx] = acc[i] + bb;
    }
}

// ======================= launcher =======================

extern "C" void kernel_launch(void* const* d_in, const int* in_sizes, int n_in,
                              void* d_out, int out_size) {
    const float* x      = (const float*)d_in[0];
    const void*  ei     = d_in[1];
    const float* W1     = (const float*)d_in[2];
    const float* b1     = (const float*)d_in[3];
    const float* coeffs = (const float*)d_in[4];
    const float* W2     = (const float*)d_in[5];
    const float* b2     = (const float*)d_in[6];
    float*       out    = (float*)d_out;

    zero_detect_kernel<<<NBLK_SCAN, 256>>>((const int*)ei);
    count_deg_kernel<<<NE / 256, 256>>>(ei);
    scan1_kernel<<<NBLK_SCAN, 256>>>();
    scan23_kernel<<<(NN + 511) / 512, 512>>>();
    scatter_kernel<<<NE / 256, 256>>>(ei);

    gemm1_kernel<<<(NN + 63) / 64, 128>>>(x, W1, b1);

    const double a = 0.5, b = 0.5;
    for (int l = 0; l < NLAYERS; l++) {
        prop_first_kernel<<<NBLK_PROP, 128>>>();
        for (int k = 2; k <= KORD; k++) {
            double n = (double)(k - 1);
            double An = (2 * n + a + b + 1) * (2 * n + a + b + 2)
                        / (2 * (n + 1) * (n + a + b + 1));
            double Bn = (a * a - b * b) * (2 * n + a + b + 1)
                        / (2 * (n + 1) * (n + a + b + 1) * (2 * n + a + b));
            double Cn = (n + a) * (n + b) * (2 * n + a + b + 2)
                        / ((n + 1) * (n + a + b + 1) * (2 * n + a + b));
            prop_step_kernel<<<NBLK_PROP, 128>>>((float)An, (float)Bn, (float)Cn,
                                                 k - 1, k - 2, k);
        }
        layer_epi_kernel<<<(NN * 32 + 255) / 256, 256>>>(coeffs, l * (KORD + 1));
    }

    gemm2_kernel<<<(NN + 31) / 32, 256>>>(W2, b2, out);
}

// round 7
// speedup vs baseline: 2.4053x; 1.0201x over previous
#include <cuda_runtime.h>
#include <cuda_fp16.h>
#include <cstdint>
#include <math.h>

// ---------------- problem constants (fixed by reference) ----------------
#define NN      100000      // N_NODES
#define NE      1600000     // N_EDGES
#define HID     64
#define INC     256
#define OUTC    32
#define KORD    10
#define NLAYERS 2
#define NBLK_SCAN 391       // ceil(NN/256)
#define NBLK_PROP 25000     // ceil(NN/4), 4 nodes (warps) per block
#define NEP_MAX (NE + 8 * NN)   // padded CSR capacity (2.4M)

// ---------------- device scratch (static globals: allowed) --------------
__device__ int   g_is64;
__device__ int   g_deg[NN];
__device__ float g_dinv[NN];        // 1/sqrt(deg+1)
__device__ float g_ds[NN];          // sqrt(deg+1)
__device__ int   g_off[NN + 1];     // padded-CSR offsets (multiples of 8)
__device__ int   g_cur[NN];
__device__ int   g_src[NEP_MAX];
__device__ int   g_bsum[512];

// slot k holds dinv * t_k as half2 (32 half2 = 64 ch per node).
// Row NN is the zero sentinel row for CSR padding — never written.
__device__ __align__(16) __half2 g_H[KORD + 1][(NN + 8) * 32];

// ============== dtype detect + zero deg + src sentinel fill (fused) =====
__global__ void zero_detect_kernel(const int* __restrict__ ei32) {
    int i = blockIdx.x * 256 + threadIdx.x;
    if (i < NN) g_deg[i] = 0;
    if (i < NEP_MAX) g_src[i] = NN;          // sentinel (zero row)
    if (blockIdx.x == 0) {
        __shared__ int nz;
        if (threadIdx.x == 0) nz = 0;
        __syncthreads();
        for (int t = threadIdx.x; t < 4096; t += 256)
            if (ei32[2 * t + 1] != 0) nz = 1;
        __syncthreads();
        if (threadIdx.x == 0) g_is64 = nz ? 0 : 1;
    }
}

__device__ __forceinline__ int edge_at(const void* __restrict__ ei, int idx, int is64) {
    if (is64) return (int)((const long long*)ei)[idx];
    return ((const int*)ei)[idx];
}

// ======================= CSR build =======================

__global__ void count_deg_kernel(const void* __restrict__ ei) {
    int is64 = g_is64;
    int e = blockIdx.x * 256 + threadIdx.x;
    if (e < NE) {
        int c = edge_at(ei, NE + e, is64);
        atomicAdd(&g_deg[c], 1);
    }
}

// scan of PADDED degrees (rounded up to multiple of 8); dinv/ds from real deg
__global__ void scan1_kernel() {
    __shared__ int sh[256];
    int tid = threadIdx.x;
    int i = blockIdx.x * 256 + tid;
    int v = (i < NN) ? g_deg[i] : 0;
    if (i < NN) {
        float d = (float)(v + 1);
        g_dinv[i] = rsqrtf(d);
        g_ds[i]   = sqrtf(d);
    }
    int pv = (v + 7) & ~7;                   // padded degree
    sh[tid] = pv;
    __syncthreads();
#pragma unroll
    for (int o = 1; o < 256; o <<= 1) {
        int t = (tid >= o) ? sh[tid - o] : 0;
        __syncthreads();
        sh[tid] += t;
        __syncthreads();
    }
    if (i < NN) g_off[i] = sh[tid] - pv;
    if (tid == 255) g_bsum[blockIdx.x] = sh[255];
}

__global__ void scan23_kernel() {
    __shared__ int sh[512];
    int tid = threadIdx.x;
    int v = (tid < NBLK_SCAN) ? g_bsum[tid] : 0;
    sh[tid] = v;
    __syncthreads();
#pragma unroll
    for (int o = 1; o < 512; o <<= 1) {
        int t = (tid >= o) ? sh[tid - o] : 0;
        __syncthreads();
        sh[tid] += t;
        __syncthreads();
    }
    int i = blockIdx.x * 512 + tid;
    if (i < NN) {
        int sb = i >> 8;
        int add = (sb > 0) ? sh[sb - 1] : 0;
        int o = g_off[i] + add;
        g_off[i] = o;
        g_cur[i] = o;
    }
    if (blockIdx.x == 0 && tid == 0) g_off[NN] = sh[NBLK_SCAN - 1];  // total padded
}

__global__ void scatter_kernel(const void* __restrict__ ei) {
    int is64 = g_is64;
    int e = blockIdx.x * 256 + threadIdx.x;
    if (e < NE) {
        int r = edge_at(ei, e, is64);
        int c = edge_at(ei, NE + e, is64);
        int p = atomicAdd(&g_cur[c], 1);
        g_src[p] = r;
    }
}

// ======================= GEMM1 (tensor cores, fp16 in / fp32 acc) ========
// g_H[0] = half(dinv * relu(x @ W1 + b1)).

#define KC 32

__global__ __launch_bounds__(128) void gemm1_kernel(const float* __restrict__ x,
                                                    const float* __restrict__ W1,
                                                    const float* __restrict__ b1) {
    __shared__ __align__(16) __half As[64][KC + 8];
    __shared__ __align__(16) __half Bs[64][KC + 8];
    __shared__ float bsh[64];
    int tid = threadIdx.x;
    int warp = tid >> 5, lane = tid & 31;
    int g = lane >> 2;
    int t2 = (lane & 3) * 2;
    int row0 = blockIdx.x * 64;

    if (tid < 64) bsh[tid] = b1[tid];

    float acc[8][4];
#pragma unroll
    for (int nt = 0; nt < 8; nt++)
#pragma unroll
        for (int q = 0; q < 4; q++) acc[nt][q] = 0.f;

    for (int kc = 0; kc < INC; kc += KC) {
        {
            int r = tid >> 1;
            int kp = (tid & 1) * 16;
            int gr = row0 + r;
            const float4* xr = (const float4*)(x + (long long)gr * INC + kc + kp);
            float4 v[4];
#pragma unroll
            for (int q = 0; q < 4; q++)
                v[q] = (gr < NN) ? xr[q] : make_float4(0.f, 0.f, 0.f, 0.f);
            __half2* dst = (__half2*)&As[r][kp];
#pragma unroll
            for (int q = 0; q < 4; q++) {
                dst[q * 2 + 0] = __floats2half2_rn(v[q].x, v[q].y);
                dst[q * 2 + 1] = __floats2half2_rn(v[q].z, v[q].w);
            }
        }
        for (int q = 0; q < 4; q++) {
            int idx = tid + 128 * q;
            int k = idx >> 4;
            int n0 = (idx & 15) * 4;
            float4 wv = *(const float4*)(W1 + (long long)(kc + k) * HID + n0);
            Bs[n0 + 0][k] = __float2half_rn(wv.x);
            Bs[n0 + 1][k] = __float2half_rn(wv.y);
            Bs[n0 + 2][k] = __float2half_rn(wv.z);
            Bs[n0 + 3][k] = __float2half_rn(wv.w);
        }
        __syncthreads();

#pragma unroll
        for (int kk = 0; kk < KC; kk += 16) {
            uint32_t a0 = *(const uint32_t*)&As[16 * warp + g    ][kk + t2];
            uint32_t a1 = *(const uint32_t*)&As[16 * warp + g + 8][kk + t2];
            uint32_t a2 = *(const uint32_t*)&As[16 * warp + g    ][kk + t2 + 8];
            uint32_t a3 = *(const uint32_t*)&As[16 * warp + g + 8][kk + t2 + 8];
#pragma unroll
            for (int nt = 0; nt < 8; nt++) {
                uint32_t b0 = *(const uint32_t*)&Bs[nt * 8 + g][kk + t2];
                uint32_t b1f = *(const uint32_t*)&Bs[nt * 8 + g][kk + t2 + 8];
                asm volatile(
                    "mma.sync.aligned.m16n8k16.row.col.f32.f16.f16.f32 "
                    "{%0,%1,%2,%3}, {%4,%5,%6,%7}, {%8,%9}, {%0,%1,%2,%3};"
                    : "+f"(acc[nt][0]), "+f"(acc[nt][1]),
                      "+f"(acc[nt][2]), "+f"(acc[nt][3])
                    : "r"(a0), "r"(a1), "r"(a2), "r"(a3), "r"(b0), "r"(b1f));
            }
        }
        __syncthreads();
    }

    int r1 = row0 + 16 * warp + g;
    int r2 = r1 + 8;
    float dv1 = (r1 < NN) ? g_dinv[r1] : 0.f;
    float dv2 = (r2 < NN) ? g_dinv[r2] : 0.f;
#pragma unroll
    for (int nt = 0; nt < 8; nt++) {
        int c0 = nt * 8 + t2;
        float bb0 = bsh[c0], bb1 = bsh[c0 + 1];
        if (r1 < NN) {
            float h0 = fmaxf(acc[nt][0] + bb0, 0.f);
            float h1 = fmaxf(acc[nt][1] + bb1, 0.f);
            g_H[0][r1 * 32 + (c0 >> 1)] = __floats2half2_rn(dv1 * h0, dv1 * h1);
        }
        if (r2 < NN) {
            float h0 = fmaxf(acc[nt][2] + bb0, 0.f);
            float h1 = fmaxf(acc[nt][3] + bb1, 0.f);
            g_H[0][r2 * 32 + (c0 >> 1)] = __floats2half2_rn(dv2 * h0, dv2 * h1);
        }
    }
}

// ======================= Jacobi propagation (hot loop) ===================
// Warp per node, half2 per lane (128B/row). Padded CSR: edge count is a
// multiple of 8 -> tail-free 8-unrolled gather, aligned int4 index loads,
// 8 independent L2 lines in flight per warp.

__device__ __forceinline__ void gather8(const __half2* __restrict__ g,
                                        const int* __restrict__ src,
                                        int s, int e, int lane,
                                        float& gx, float& gy) {
    float a0x = 0.f, a0y = 0.f, a1x = 0.f, a1y = 0.f;
    float a2x = 0.f, a2y = 0.f, a3x = 0.f, a3y = 0.f;
    for (int j = s; j < e; j += 8) {
        int4 ia = *(const int4*)(src + j);
        int4 ib = *(const int4*)(src + j + 4);
        float2 v0 = __half22float2(g[ia.x * 32 + lane]);
        float2 v1 = __half22float2(g[ia.y * 32 + lane]);
        float2 v2 = __half22float2(g[ia.z * 32 + lane]);
        float2 v3 = __half22float2(g[ia.w * 32 + lane]);
        float2 v4 = __half22float2(g[ib.x * 32 + lane]);
        float2 v5 = __half22float2(g[ib.y * 32 + lane]);
        float2 v6 = __half22float2(g[ib.z * 32 + lane]);
        float2 v7 = __half22float2(g[ib.w * 32 + lane]);
        a0x += v0.x + v4.x; a0y += v0.y + v4.y;
        a1x += v1.x + v5.x; a1y += v1.y + v5.y;
        a2x += v2.x + v6.x; a2y += v2.y + v6.y;
        a3x += v3.x + v7.x; a3y += v3.y + v7.y;
    }
    gx = (a0x + a1x) + (a2x + a3x);
    gy = (a0y + a1y) + (a2y + a3y);
}

__global__ __launch_bounds__(128) void prop_first_kernel() {
    int w = threadIdx.x >> 5, lane = threadIdx.x & 31;
    int node = blockIdx.x * 4 + w;
    if (node >= NN) return;
    const __half2* __restrict__ g = g_H[0];
    __half2* __restrict__ go = g_H[1];

    int idx2 = node * 32 + lane;
    float2 self = __half22float2(g[idx2]);
    float gx, gy;
    gather8(g, g_src, g_off[node], g_off[node + 1], lane, gx, gy);
    gx += self.x; gy += self.y;                // self loop
    float dv = g_dinv[node];
    float dv2f = dv * dv;
    go[idx2] = __floats2half2_rn(dv2f * gx, dv2f * gy);
}

__global__ __launch_bounds__(128) void prop_step_kernel(float An, float Bn, float Cn,
                                                        int kin, int kt0, int kout) {
    int w = threadIdx.x >> 5, lane = threadIdx.x & 31;
    int node = blockIdx.x * 4 + w;
    if (node >= NN) return;
    const __half2* __restrict__ g = g_H[kin];
    const __half2* __restrict__ gt0 = g_H[kt0];
    __half2* __restrict__ go = g_H[kout];

    int idx2 = node * 32 + lane;
    float2 self = __half22float2(g[idx2]);     // dinv * t1
    float gx, gy;
    gather8(g, g_src, g_off[node], g_off[node + 1], lane, gx, gy);
    gx += self.x; gy += self.y;                // self loop

    float dv = g_dinv[node], ds = g_ds[node];
    float px = dv * gx, py = dv * gy;          // (P t1)
    float t1x = self.x * ds, t1y = self.y * ds;
    float2 g0 = __half22float2(gt0[idx2]);
    float t0x = g0.x * ds, t0y = g0.y * ds;
    float t2x = An * px + Bn * t1x - Cn * t0x;
    float t2y = An * py + Bn * t1y - Cn * t0y;
    go[idx2] = __floats2half2_rn(dv * t2x, dv * t2y);
}

// ======================= layer epilogue ==================================
// slot0' = relu(sum_k c_k slot_k)  (= dinv * relu(sum c_k t_k), dinv>0)
__global__ void layer_epi_kernel(const float* __restrict__ coeffs, int base) {
    int i = blockIdx.x * 256 + threadIdx.x;     // half2 index
    if (i >= NN * 32) return;
    float c[KORD + 1];
#pragma unroll
    for (int k = 0; k <= KORD; k++) c[k] = coeffs[base + k];
    float ax = 0.f, ay = 0.f;
#pragma unroll
    for (int k = 0; k <= KORD; k++) {
        float2 v = __half22float2(g_H[k][i]);
        ax += c[k] * v.x;
        ay += c[k] * v.y;
    }
    g_H[0][i] = __floats2half2_rn(fmaxf(ax, 0.f), fmaxf(ay, 0.f));
}

// ======================= GEMM2: out = (ds*slot0) @ W2 + b2 ===============
__global__ __launch_bounds__(256) void gemm2_kernel(const float* __restrict__ W2,
                                                    const float* __restrict__ b2,
                                                    float* __restrict__ out) {
    __shared__ __align__(16) float ws[64][32];
    __shared__ __align__(16) float xs[32][65];
    int tx = threadIdx.x & 31;
    int ty = threadIdx.x >> 5;
    int row0 = blockIdx.x * 32;

    for (int l = threadIdx.x; l < 64 * 32; l += 256) ws[l >> 5][l & 31] = W2[l];
    for (int l = threadIdx.x; l < 32 * 32; l += 256) {
        int r = l >> 5, kk = l & 31;
        int gr = row0 + r;
        float2 v = (gr < NN) ? __half22float2(g_H[0][gr * 32 + kk])
                             : make_float2(0.f, 0.f);
        float dsv = (gr < NN) ? g_ds[gr] : 0.f;
        xs[r][kk * 2]     = dsv * v.x;
        xs[r][kk * 2 + 1] = dsv * v.y;
    }
    __syncthreads();

    float acc[4] = {0.f, 0.f, 0.f, 0.f};
#pragma unroll
    for (int k = 0; k < 64; k++) {
        float wv = ws[k][tx];
#pragma unroll
        for (int i = 0; i < 4; i++) acc[i] += xs[ty * 4 + i][k] * wv;
    }
    float bb = b2[tx];
#pragma unroll
    for (int i = 0; i < 4; i++) {
        int gr = row0 + ty * 4 + i;
        if (gr < NN) out[gr * OUTC + tx] = acc[i] + bb;
    }
}

// ======================= launcher =======================

extern "C" void kernel_launch(void* const* d_in, const int* in_sizes, int n_in,
                              void* d_out, int out_size) {
    const float* x      = (const float*)d_in[0];
    const void*  ei     = d_in[1];
    const float* W1     = (const float*)d_in[2];
    const float* b1     = (const float*)d_in[3];
    const float* coeffs = (const float*)d_in[4];
    const float* W2     = (const float*)d_in[5];
    const float* b2     = (const float*)d_in[6];
    float*       out    = (float*)d_out;

    zero_detect_kernel<<<(NEP_MAX + 255) / 256, 256>>>((const int*)ei);
    count_deg_kernel<<<NE / 256, 256>>>(ei);
    scan1_kernel<<<NBLK_SCAN, 256>>>();
    scan23_kernel<<<(NN + 511) / 512, 512>>>();
    scatter_kernel<<<NE / 256, 256>>>(ei);

    gemm1_kernel<<<(NN + 63) / 64, 128>>>(x, W1, b1);

    const double a = 0.5, b = 0.5;
    for (int l = 0; l < NLAYERS; l++) {
        prop_first_kernel<<<NBLK_PROP, 128>>>();
        for (int k = 2; k <= KORD; k++) {
            double n = (double)(k - 1);
            double An = (2 * n + a + b + 1) * (2 * n + a + b + 2)
                        / (2 * (n + 1) * (n + a + b + 1));
            double Bn = (a * a - b * b) * (2 * n + a + b + 1)
                        / (2 * (n + 1) * (n + a + b + 1) * (2 * n + a + b));
            double Cn = (n + a) * (n + b) * (2 * n + a + b + 2)
                        / ((n + 1) * (n + a + b + 1) * (2 * n + a + b));
            prop_step_kernel<<<NBLK_PROP, 128>>>((float)An, (float)Bn, (float)Cn,
                                                 k - 1, k - 2, k);
        }
        layer_epi_kernel<<<(NN * 32 + 255) / 256, 256>>>(coeffs, l * (KORD + 1));
    }

    gemm2_kernel<<<(NN + 31) / 32, 256>>>(W2, b2, out);
}